// round 16
// baseline (speedup 1.0000x reference)
#include <cuda_runtime.h>
#include <cuda_fp16.h>
#include <cstdint>

#define B_SZ 1024
#define F_SZ 256
#define D_SZ 64
#define NFULL (F_SZ * D_SZ)
#define GRID_PREP 148
#define GRID_MAIN 296            // 2 CTAs per SM
#define NUNITS 2048              // 2 halves x 1024 batches, h-major

// ---------------- device scratch ----------------
__device__ float    g_qkv[3 * F_SZ * D_SZ];    // qkv[t][f][d]
__device__ float    g_trans[2 * F_SZ * D_SZ];  // trans[t][f][d]
__device__ float    g_S1[B_SZ * F_SZ];         // s1[b][j]
__device__ float    g_SA[B_SZ * F_SZ];         // s0*s2 [b][i]
__device__ __half   g_Mh[F_SZ * F_SZ];         // gated cross, fp16
__device__ unsigned g_bcnt;                    // barrier arrive counter
__device__ unsigned g_bgen;                    // barrier generation (monotonic)

// ---------------- smem layout for k_main (bytes) ----------------
#define A_RB 528                  // M row: 256 halfs + 8 pad
#define Z_RB 144                  // Z row: 64 halfs + 8 pad
#define SM_A 0                    // 128 * 528 = 67584 (one M half)
#define SM_Z 67584                // 256 * 144 = 36864 (single buffer)
#define SMEM_TOTAL (SM_Z + F_SZ * Z_RB)   // 104448 -> 2 CTAs/SM

// ---------------- helpers ----------------
__device__ __forceinline__ uint32_t smem_u32(const void* p) {
    uint32_t a;
    asm("{ .reg .u64 t; cvta.to.shared.u64 t, %1; cvt.u32.u64 %0, t; }"
        : "=r"(a) : "l"(p));
    return a;
}
#define LDSM4(r, a) \
    asm volatile("ldmatrix.sync.aligned.m8n8.x4.shared.b16 {%0,%1,%2,%3}, [%4];" \
                 : "=r"((r)[0]), "=r"((r)[1]), "=r"((r)[2]), "=r"((r)[3]) : "r"(a))
#define LDSM4T(r, a) \
    asm volatile("ldmatrix.sync.aligned.m8n8.x4.trans.shared.b16 {%0,%1,%2,%3}, [%4];" \
                 : "=r"((r)[0]), "=r"((r)[1]), "=r"((r)[2]), "=r"((r)[3]) : "r"(a))
#define HMMA(d, a, b0, b1) \
    asm volatile("mma.sync.aligned.m16n8k16.row.col.f32.f16.f16.f32 " \
                 "{%0,%1,%2,%3}, {%4,%5,%6,%7}, {%8,%9}, {%0,%1,%2,%3};" \
                 : "+f"((d)[0]), "+f"((d)[1]), "+f"((d)[2]), "+f"((d)[3]) \
                 : "r"((a)[0]), "r"((a)[1]), "r"((a)[2]), "r"((a)[3]), \
                   "r"(b0), "r"(b1))

__device__ __forceinline__ uint32_t pack2h(float a, float b) {
    __half2 h = __floats2half2_rn(a, b);
    return *(uint32_t*)&h;
}

// sense-reversal grid barrier; safe for repeated graph replays (gen monotonic,
// count self-resets). All GRID_PREP CTAs resident simultaneously.
__device__ __forceinline__ void grid_bar() {
    __syncthreads();
    if (threadIdx.x == 0) {
        __threadfence();
        unsigned gen = atomicAdd(&g_bgen, 0u);
        unsigned arrived = atomicAdd(&g_bcnt, 1u);
        if (arrived == GRID_PREP - 1) {
            atomicExch(&g_bcnt, 0u);
            __threadfence();
            atomicAdd(&g_bgen, 1u);
        } else {
            while (atomicAdd(&g_bgen, 0u) == gen) __nanosleep(32);
        }
        __threadfence();
    }
    __syncthreads();
}

// build one Z element (8 halfs = 16 bytes): Z[j][dq*8..+8)
__device__ __forceinline__ void z_elem(char* zbuf, const float* q2,
                                       const float* s1p, int idx) {
    int j = idx >> 3, dq = idx & 7;
    float s1 = __ldg(s1p + j);
    const float4* qp = (const float4*)(q2 + j * 64) + dq * 2;
    float4 qa = qp[0], qb = qp[1];
    uint4 v;
    v.x = pack2h(qa.x * s1, qa.y * s1);
    v.y = pack2h(qa.z * s1, qa.w * s1);
    v.z = pack2h(qb.x * s1, qb.y * s1);
    v.w = pack2h(qb.z * s1, qb.w * s1);
    *(uint4*)(zbuf + j * Z_RB + dq * 16) = v;
}

// ---------------- K1: fused prep (qkv -> barrier -> gate + S pool) ----------------
__global__ void __launch_bounds__(256)
k_prep(const float* __restrict__ feature, const float* __restrict__ ind,
       const float* __restrict__ Wqk, const float* __restrict__ Wqkv) {
    int tid = threadIdx.x, c = blockIdx.x;
    int w = tid >> 5, l = tid & 31;
    __shared__ float q1i[D_SZ], t0i[D_SZ];

    // ---- phase 1: qkv/trans = indicator @ W (1280 rows over grid) ----
    {
        int grp = tid >> 6, e = tid & 63;
        for (int r = c + grp * GRID_PREP; r < 1280; r += 4 * GRID_PREP) {
            int m = r >> 8, f = r & 255;
            const float* W = (m < 3) ? (Wqkv + m * 4096) : (Wqk + (m - 3) * 4096);
            const float* indf = ind + f * 64;
            float acc = 0.f;
#pragma unroll 16
            for (int d = 0; d < 64; d++)
                acc = fmaf(__ldg(indf + d), __ldg(W + d * 64 + e), acc);
            if (m < 3) g_qkv[m * 16384 + f * 64 + e] = acc;
            else       g_trans[(m - 3) * 16384 + f * 64 + e] = acc;
        }
    }
    grid_bar();

    // ---- phase 2: task pool — 256 gate rows + 512 S pairs ----
    for (int task = c; task < 768; task += GRID_PREP) {
        if (task < 256) {
            int i = task;
            __syncthreads();
            if (tid < 64) q1i[tid] = g_qkv[F_SZ * D_SZ + i * D_SZ + tid];
            else if (tid < 128) t0i[tid - 64] = g_trans[i * D_SZ + (tid - 64)];
            __syncthreads();
            const float* q0 = g_qkv;
            const float* t1 = g_trans + F_SZ * D_SZ;
#pragma unroll
            for (int jj = 0; jj < 32; jj++) {
                int j = w * 32 + jj;
                float cc = q1i[l] * q0[j * D_SZ + l]
                         + q1i[l + 32] * q0[j * D_SZ + l + 32];
                float gl = t0i[l] * t1[j * D_SZ + l]
                         + t0i[l + 32] * t1[j * D_SZ + l + 32];
#pragma unroll
                for (int o = 16; o > 0; o >>= 1) {
                    cc += __shfl_xor_sync(0xFFFFFFFFu, cc, o);
                    gl += __shfl_xor_sync(0xFFFFFFFFu, gl, o);
                }
                if (l == 0)
                    g_Mh[i * F_SZ + j] = __float2half_rn((gl > 0.f) ? cc : 0.f);
            }
        } else {
            int b0 = (task - 256) * 2;
            int hb = l >> 4, ll = l & 15;
            int b = b0 + hb;
            for (int ii = 0; ii < 32; ii++) {
                int i = w * 32 + ii;
                const float4* qp = (const float4*)(g_qkv + i * D_SZ) + ll;
                float4 q0 = qp[0];
                float4 q1 = qp[(F_SZ * D_SZ) / 4];
                float4 q2 = qp[(2 * F_SZ * D_SZ) / 4];
                float4 f = *((const float4*)(feature + (size_t)b * (F_SZ * D_SZ)
                                             + i * D_SZ) + ll);
                float d0 = f.x * q0.x + f.y * q0.y + f.z * q0.z + f.w * q0.w;
                float d1 = f.x * q1.x + f.y * q1.y + f.z * q1.z + f.w * q1.w;
                float d2 = f.x * q2.x + f.y * q2.y + f.z * q2.z + f.w * q2.w;
#pragma unroll
                for (int o = 8; o > 0; o >>= 1) {
                    d0 += __shfl_xor_sync(0xFFFFFFFFu, d0, o);
                    d1 += __shfl_xor_sync(0xFFFFFFFFu, d1, o);
                    d2 += __shfl_xor_sync(0xFFFFFFFFu, d2, o);
                }
                if (ll == 0) {
                    g_S1[b * F_SZ + i] = d1;
                    g_SA[b * F_SZ + i] = d0 * d2;
                }
            }
        }
    }
}

// ---------------- K2: fp16 HMMA main kernel, 2 CTAs/SM (R15 best, unchanged) ----------------
__global__ void __launch_bounds__(256, 2)
k_main(float* __restrict__ out) {
    extern __shared__ char sm[];
    uint32_t sb = smem_u32(sm);
    int tid = threadIdx.x, w = tid >> 5, lane = tid & 31;
    int c = blockIdx.x;
    int u0 = (c * NUNITS) / GRID_MAIN, u1 = ((c + 1) * NUNITS) / GRID_MAIN;

    int m0 = (w >> 1) * 32, n0 = (w & 1) * 32;
    int g = lane >> 2, t4 = lane & 3;
    uint32_t aBase = sb + SM_A + (uint32_t)(m0 + (lane & 15)) * A_RB
                     + (uint32_t)(lane >> 4) * 16;
    uint32_t bBase = sb + SM_Z + (uint32_t)(lane & 15) * Z_RB
                     + (uint32_t)(n0 + 8 * (lane >> 4)) * 2;
    const float* q2 = g_qkv + 2 * F_SZ * D_SZ;

    int curH = -1;
    for (int u = u0; u < u1; u++) {
        int h = u >> 10, b = u & 1023;

        __syncthreads();   // prior readers of Z (and A) done
        if (h != curH) {
            const uint4* msrc = (const uint4*)(g_Mh + (size_t)h * 128 * F_SZ);
            for (int i = tid; i < 4096; i += 256) {
                int r = i >> 5, c8 = i & 31;
                *(uint4*)(sm + SM_A + r * A_RB + c8 * 16) = msrc[i];
            }
            curH = h;
        }
        // build Z for this batch
        {
            const float* s1p = g_S1 + b * F_SZ;
#pragma unroll
            for (int rep = 0; rep < 8; rep++)
                z_elem(sm + SM_Z, q2, s1p, rep * 256 + tid);
        }
        __syncthreads();

        // ---- mainloop: 16 k-iters, warp tile 32x32 ----
        float acc[8][4];
#pragma unroll
        for (int i = 0; i < 8; i++)
#pragma unroll
            for (int q = 0; q < 4; q++) acc[i][q] = 0.f;

#pragma unroll
        for (int k = 0; k < 16; k++) {
            uint32_t kA = (uint32_t)k * 32;
            uint32_t kB = (uint32_t)k * 16 * Z_RB;
            uint32_t a0[4], a1[4], bq0[4], bq1[4];
            LDSM4(a0, aBase + kA);
            LDSM4(a1, aBase + 16 * A_RB + kA);
            LDSM4T(bq0, bBase + kB);
            LDSM4T(bq1, bBase + kB + 32);

            HMMA(acc[0], a0, bq0[0], bq0[1]);
            HMMA(acc[1], a0, bq0[2], bq0[3]);
            HMMA(acc[2], a0, bq1[0], bq1[1]);
            HMMA(acc[3], a0, bq1[2], bq1[3]);
            HMMA(acc[4], a1, bq0[0], bq0[1]);
            HMMA(acc[5], a1, bq0[2], bq0[3]);
            HMMA(acc[6], a1, bq1[0], bq1[1]);
            HMMA(acc[7], a1, bq1[2], bq1[3]);
        }

        // ---- epilogue: scale by SA, store ----
        const float* sap = g_SA + b * F_SZ + h * 128;
        float* ob = out + (size_t)b * NFULL + h * 128 * D_SZ;
#pragma unroll
        for (int mt = 0; mt < 2; mt++) {
            int r0 = m0 + mt * 16 + g;
            float f0 = __ldg(sap + r0), f1 = __ldg(sap + r0 + 8);
#pragma unroll
            for (int nt = 0; nt < 4; nt++) {
                float* a = acc[mt * 4 + nt];
                int col = n0 + nt * 8 + 2 * t4;
                *(float2*)(ob + r0 * 64 + col) =
                    make_float2(a[0] * f0, a[1] * f0);
                *(float2*)(ob + (r0 + 8) * 64 + col) =
                    make_float2(a[2] * f1, a[3] * f1);
            }
        }
    }
}

// ---------------- launch ----------------
extern "C" void kernel_launch(void* const* d_in, const int* in_sizes, int n_in,
                              void* d_out, int out_size) {
    const float *feature = nullptr, *indicator = nullptr;
    const float *Wqk = nullptr, *Wqkv = nullptr;
    for (int k = 0; k < n_in; k++) {
        switch (in_sizes[k]) {
            case B_SZ * F_SZ * D_SZ: feature   = (const float*)d_in[k]; break;
            case F_SZ * D_SZ:        indicator = (const float*)d_in[k]; break;
            case 2 * D_SZ * D_SZ:    Wqk       = (const float*)d_in[k]; break;
            case 3 * D_SZ * D_SZ:    Wqkv      = (const float*)d_in[k]; break;
        }
    }
    float* out = (float*)d_out;

    cudaFuncSetAttribute(k_main, cudaFuncAttributeMaxDynamicSharedMemorySize,
                         SMEM_TOTAL);

    k_prep<<<GRID_PREP, 256>>>(feature, indicator, Wqk, Wqkv);
    k_main<<<GRID_MAIN, 256, SMEM_TOTAL>>>(out);
}

// round 17
// speedup vs baseline: 1.8615x; 1.8615x over previous
#include <cuda_runtime.h>
#include <cuda_fp16.h>
#include <cstdint>

#define B_SZ 1024
#define F_SZ 256
#define D_SZ 64
#define NFULL (F_SZ * D_SZ)
#define GRID_MAIN 296            // 2 CTAs per SM
#define NUNITS 2048              // 2 halves x 1024 batches, h-major

// ---------------- device scratch ----------------
__device__ float  g_qkv[3 * F_SZ * D_SZ];    // qkv[t][f][d]
__device__ float  g_trans[2 * F_SZ * D_SZ];  // trans[t][f][d]
__device__ float  g_S1[B_SZ * F_SZ];         // s1[b][j]
__device__ float  g_SA[B_SZ * F_SZ];         // s0*s2 [b][i]
__device__ __half g_Mh[F_SZ * F_SZ];         // gated cross, fp16

// ---------------- smem layout for k_main (bytes) ----------------
#define A_RB 528                  // M row: 256 halfs + 8 pad
#define Z_RB 144                  // Z row: 64 halfs + 8 pad
#define SM_A 0                    // 128 * 528 = 67584 (one M half)
#define SM_Z 67584                // 256 * 144 = 36864 (single buffer)
#define SMEM_TOTAL (SM_Z + F_SZ * Z_RB)   // 104448 -> 2 CTAs/SM

// ---------------- helpers ----------------
__device__ __forceinline__ uint32_t smem_u32(const void* p) {
    uint32_t a;
    asm("{ .reg .u64 t; cvta.to.shared.u64 t, %1; cvt.u32.u64 %0, t; }"
        : "=r"(a) : "l"(p));
    return a;
}
#define LDSM4(r, a) \
    asm volatile("ldmatrix.sync.aligned.m8n8.x4.shared.b16 {%0,%1,%2,%3}, [%4];" \
                 : "=r"((r)[0]), "=r"((r)[1]), "=r"((r)[2]), "=r"((r)[3]) : "r"(a))
#define LDSM4T(r, a) \
    asm volatile("ldmatrix.sync.aligned.m8n8.x4.trans.shared.b16 {%0,%1,%2,%3}, [%4];" \
                 : "=r"((r)[0]), "=r"((r)[1]), "=r"((r)[2]), "=r"((r)[3]) : "r"(a))
#define HMMA(d, a, b0, b1) \
    asm volatile("mma.sync.aligned.m16n8k16.row.col.f32.f16.f16.f32 " \
                 "{%0,%1,%2,%3}, {%4,%5,%6,%7}, {%8,%9}, {%0,%1,%2,%3};" \
                 : "+f"((d)[0]), "+f"((d)[1]), "+f"((d)[2]), "+f"((d)[3]) \
                 : "r"((a)[0]), "r"((a)[1]), "r"((a)[2]), "r"((a)[3]), \
                   "r"(b0), "r"(b1))

__device__ __forceinline__ uint32_t pack2h(float a, float b) {
    __half2 h = __floats2half2_rn(a, b);
    return *(uint32_t*)&h;
}

// build one Z element (8 halfs = 16 bytes): Z[j][dq*8..+8)
__device__ __forceinline__ void z_elem(char* zbuf, const float* q2,
                                       const float* s1p, int idx) {
    int j = idx >> 3, dq = idx & 7;
    float s1 = __ldg(s1p + j);
    const float4* qp = (const float4*)(q2 + j * 64) + dq * 2;
    float4 qa = qp[0], qb = qp[1];
    uint4 v;
    v.x = pack2h(qa.x * s1, qa.y * s1);
    v.y = pack2h(qa.z * s1, qa.w * s1);
    v.z = pack2h(qb.x * s1, qb.y * s1);
    v.w = pack2h(qb.z * s1, qb.w * s1);
    *(uint4*)(zbuf + j * Z_RB + dq * 16) = v;
}

// ---------------- K1: qkv / trans = indicator @ W ----------------
__global__ void k_qkv(const float* __restrict__ ind,
                      const float* __restrict__ Wqk,
                      const float* __restrict__ Wqkv) {
    int m = blockIdx.y;
    int fl = threadIdx.x >> 6, e = threadIdx.x & 63;
    int f = blockIdx.x * 4 + fl;
    __shared__ float indS[4 * D_SZ];
    indS[threadIdx.x] = ind[f * D_SZ + e];
    __syncthreads();
    const float* W = (m < 3) ? (Wqkv + m * D_SZ * D_SZ)
                             : (Wqk + (m - 3) * D_SZ * D_SZ);
    float acc = 0.f;
#pragma unroll
    for (int d = 0; d < D_SZ; d++) acc = fmaf(indS[fl * 64 + d], W[d * D_SZ + e], acc);
    if (m < 3) g_qkv[m * F_SZ * D_SZ + f * D_SZ + e] = acc;
    else       g_trans[(m - 3) * F_SZ * D_SZ + f * D_SZ + e] = acc;
}

// ---------------- K2: merged gate + s kernel ----------------
// blocks [0,256): gate rows (fp16 M); blocks [256,1280): S1/SA, ONE batch each.
__global__ void __launch_bounds__(256) k_prep(const float* __restrict__ feature) {
    int tid = threadIdx.x, w = tid >> 5, l = tid & 31;
    if (blockIdx.x < 256) {
        int i = blockIdx.x;
        __shared__ float q1i[D_SZ], t0i[D_SZ];
        if (tid < 64) q1i[tid] = g_qkv[F_SZ * D_SZ + i * D_SZ + tid];
        else if (tid < 128) t0i[tid - 64] = g_trans[i * D_SZ + (tid - 64)];
        __syncthreads();
        const float* q0 = g_qkv;
        const float* t1 = g_trans + F_SZ * D_SZ;
        for (int jj = 0; jj < 32; jj++) {
            int j = w * 32 + jj;
            float c  = q1i[l] * q0[j * D_SZ + l] + q1i[l + 32] * q0[j * D_SZ + l + 32];
            float gl = t0i[l] * t1[j * D_SZ + l] + t0i[l + 32] * t1[j * D_SZ + l + 32];
#pragma unroll
            for (int o = 16; o > 0; o >>= 1) {
                c  += __shfl_xor_sync(0xFFFFFFFFu, c, o);
                gl += __shfl_xor_sync(0xFFFFFFFFu, gl, o);
            }
            if (l == 0)
                g_Mh[i * F_SZ + j] = __float2half_rn((gl > 0.f) ? c : 0.f);
        }
    } else {
        // ---- S: one batch per block; 2 rows per warp-iteration (16-lane halves) ----
        int b = blockIdx.x - 256;
        int hb = l >> 4, ll = l & 15;
        const float* fb = feature + (size_t)b * (F_SZ * D_SZ);
#pragma unroll 2
        for (int ii = 0; ii < 16; ii++) {
            int i = w * 32 + hb * 16 + ii;         // two rows per warp per iter
            const float4* qp = (const float4*)(g_qkv + i * D_SZ) + ll;
            float4 q0 = qp[0];
            float4 q1 = qp[(F_SZ * D_SZ) / 4];
            float4 q2 = qp[(2 * F_SZ * D_SZ) / 4];
            float4 f = *((const float4*)(fb + i * D_SZ) + ll);
            float d0 = f.x * q0.x + f.y * q0.y + f.z * q0.z + f.w * q0.w;
            float d1 = f.x * q1.x + f.y * q1.y + f.z * q1.z + f.w * q1.w;
            float d2 = f.x * q2.x + f.y * q2.y + f.z * q2.z + f.w * q2.w;
#pragma unroll
            for (int o = 8; o > 0; o >>= 1) {
                d0 += __shfl_xor_sync(0xFFFFFFFFu, d0, o);
                d1 += __shfl_xor_sync(0xFFFFFFFFu, d1, o);
                d2 += __shfl_xor_sync(0xFFFFFFFFu, d2, o);
            }
            if (ll == 0) {
                g_S1[b * F_SZ + i] = d1;
                g_SA[b * F_SZ + i] = d0 * d2;
            }
        }
    }
}

// ---------------- K3: fp16 HMMA main kernel, 2 CTAs/SM (measured 44.4us) ----------------
__global__ void __launch_bounds__(256, 2)
k_main(float* __restrict__ out) {
    extern __shared__ char sm[];
    uint32_t sb = smem_u32(sm);
    int tid = threadIdx.x, w = tid >> 5, lane = tid & 31;
    int c = blockIdx.x;
    int u0 = (c * NUNITS) / GRID_MAIN, u1 = ((c + 1) * NUNITS) / GRID_MAIN;

    int m0 = (w >> 1) * 32, n0 = (w & 1) * 32;
    int g = lane >> 2, t4 = lane & 3;
    uint32_t aBase = sb + SM_A + (uint32_t)(m0 + (lane & 15)) * A_RB
                     + (uint32_t)(lane >> 4) * 16;
    uint32_t bBase = sb + SM_Z + (uint32_t)(lane & 15) * Z_RB
                     + (uint32_t)(n0 + 8 * (lane >> 4)) * 2;
    const float* q2 = g_qkv + 2 * F_SZ * D_SZ;

    int curH = -1;
    for (int u = u0; u < u1; u++) {
        int h = u >> 10, b = u & 1023;

        __syncthreads();   // prior readers of Z (and A) done
        if (h != curH) {
            const uint4* msrc = (const uint4*)(g_Mh + (size_t)h * 128 * F_SZ);
            for (int i = tid; i < 4096; i += 256) {
                int r = i >> 5, c8 = i & 31;
                *(uint4*)(sm + SM_A + r * A_RB + c8 * 16) = msrc[i];
            }
            curH = h;
        }
        // build Z for this batch
        {
            const float* s1p = g_S1 + b * F_SZ;
#pragma unroll
            for (int rep = 0; rep < 8; rep++)
                z_elem(sm + SM_Z, q2, s1p, rep * 256 + tid);
        }
        __syncthreads();

        // ---- mainloop: 16 k-iters, warp tile 32x32 ----
        float acc[8][4];
#pragma unroll
        for (int i = 0; i < 8; i++)
#pragma unroll
            for (int q = 0; q < 4; q++) acc[i][q] = 0.f;

#pragma unroll
        for (int k = 0; k < 16; k++) {
            uint32_t kA = (uint32_t)k * 32;
            uint32_t kB = (uint32_t)k * 16 * Z_RB;
            uint32_t a0[4], a1[4], bq0[4], bq1[4];
            LDSM4(a0, aBase + kA);
            LDSM4(a1, aBase + 16 * A_RB + kA);
            LDSM4T(bq0, bBase + kB);
            LDSM4T(bq1, bBase + kB + 32);

            HMMA(acc[0], a0, bq0[0], bq0[1]);
            HMMA(acc[1], a0, bq0[2], bq0[3]);
            HMMA(acc[2], a0, bq1[0], bq1[1]);
            HMMA(acc[3], a0, bq1[2], bq1[3]);
            HMMA(acc[4], a1, bq0[0], bq0[1]);
            HMMA(acc[5], a1, bq0[2], bq0[3]);
            HMMA(acc[6], a1, bq1[0], bq1[1]);
            HMMA(acc[7], a1, bq1[2], bq1[3]);
        }

        // ---- epilogue: scale by SA, store ----
        const float* sap = g_SA + b * F_SZ + h * 128;
        float* ob = out + (size_t)b * NFULL + h * 128 * D_SZ;
#pragma unroll
        for (int mt = 0; mt < 2; mt++) {
            int r0 = m0 + mt * 16 + g;
            float f0 = __ldg(sap + r0), f1 = __ldg(sap + r0 + 8);
#pragma unroll
            for (int nt = 0; nt < 4; nt++) {
                float* a = acc[mt * 4 + nt];
                int col = n0 + nt * 8 + 2 * t4;
                *(float2*)(ob + r0 * 64 + col) =
                    make_float2(a[0] * f0, a[1] * f0);
                *(float2*)(ob + (r0 + 8) * 64 + col) =
                    make_float2(a[2] * f1, a[3] * f1);
            }
        }
    }
}

// ---------------- launch ----------------
extern "C" void kernel_launch(void* const* d_in, const int* in_sizes, int n_in,
                              void* d_out, int out_size) {
    const float *feature = nullptr, *indicator = nullptr;
    const float *Wqk = nullptr, *Wqkv = nullptr;
    for (int k = 0; k < n_in; k++) {
        switch (in_sizes[k]) {
            case B_SZ * F_SZ * D_SZ: feature   = (const float*)d_in[k]; break;
            case F_SZ * D_SZ:        indicator = (const float*)d_in[k]; break;
            case 2 * D_SZ * D_SZ:    Wqk       = (const float*)d_in[k]; break;
            case 3 * D_SZ * D_SZ:    Wqkv      = (const float*)d_in[k]; break;
        }
    }
    float* out = (float*)d_out;

    cudaFuncSetAttribute(k_main, cudaFuncAttributeMaxDynamicSharedMemorySize,
                         SMEM_TOTAL);

    k_qkv<<<dim3(64, 5), 256>>>(indicator, Wqk, Wqkv);
    k_prep<<<1280, 256>>>(feature);
    k_main<<<GRID_MAIN, 256, SMEM_TOTAL>>>(out);
}